// round 16
// baseline (speedup 1.0000x reference)
#include <cuda_runtime.h>
#include <math.h>
#include <stdint.h>

// ---------------- problem constants ----------------
#define SQ   1024
#define HDM  2048
#define NHQ  32
#define NKVH 4
#define HDHD 128
#define NE   32
#define TOPK 8
#define IDIM 768
#define NPAIR (SQ*TOPK)   // 8192

// ---------------- device scratch ----------------
__device__ float g_h1[SQ*HDM];
__device__ float g_q [SQ*NHQ*HDHD];
__device__ float g_k [SQ*NKVH*HDHD];
__device__ float g_v [SQ*NKVH*HDHD];
__device__ float g_attn[SQ*NHQ*HDHD];
__device__ float g_h [SQ*HDM];
__device__ float g_h2[SQ*HDM];
__device__ float g_tw[NPAIR];
__device__ int   g_te[NPAIR];
__device__ int   g_counts[NE];
__device__ int   g_offsets[NE];
__device__ int   g_cursor[NE];
__device__ int   g_btok[NPAIR];
__device__ int   g_ppos[NPAIR];
__device__ float g_act[(long long)NPAIR*IDIM];
__device__ float g_ybuf[(long long)NPAIR*HDM];
__device__ float g_ropec[SQ*64];
__device__ float g_ropes[SQ*64];

// ---------------- helpers ----------------
__device__ __forceinline__ void cpasync16(void* dst, const void* src, int srcsize) {
    uint32_t d = (uint32_t)__cvta_generic_to_shared(dst);
    asm volatile("cp.async.cg.shared.global [%0], [%1], 16, %2;"
                 :: "r"(d), "l"(src), "r"(srcsize) : "memory");
}
__device__ __forceinline__ void cpasync_commit() {
    asm volatile("cp.async.commit_group;" ::: "memory");
}
// round-to-nearest-away into tf32's 19 kept bits (mma ignores low 13 bits)
__device__ __forceinline__ uint32_t rnd(float v) {
    return __float_as_uint(v) + 0x1000u;
}
#define MMA_TF32(acc, a, b) \
    asm volatile( \
        "mma.sync.aligned.m16n8k8.row.col.f32.tf32.tf32.f32 " \
        "{%0,%1,%2,%3}, {%4,%5,%6,%7}, {%8,%9}, {%0,%1,%2,%3};" \
        : "+f"((acc)[0]), "+f"((acc)[1]), "+f"((acc)[2]), "+f"((acc)[3]) \
        : "r"((a)[0]), "r"((a)[1]), "r"((a)[2]), "r"((a)[3]), \
          "r"((b)[0]), "r"((b)[1]))

// ---------------- small kernels ----------------
__global__ void zero32_kernel(int* counts, int* cursor) {
    int i = threadIdx.x;
    if (i < NE) { counts[i] = 0; cursor[i] = 0; }
}

// precompute RoPE cos/sin table [SQ][64] with the exact same formula as before
__global__ void rope_table_kernel(float* ropec, float* ropes) {
    int idx = blockIdx.x * 256 + threadIdx.x;
    if (idx >= SQ * 64) return;
    int t = idx >> 6, d2 = idx & 63;
    float angle = (float)t * powf(10000.0f, -(float)(2 * d2) / 128.0f);
    ropec[idx] = cosf(angle);
    ropes[idx] = sinf(angle);
}

__global__ void rmsnorm_kernel(const float* __restrict__ x, const float* __restrict__ w,
                               float* __restrict__ o, int ncols) {
    int row = blockIdx.x;
    const float* xr = x + (long long)row * ncols;
    float* orow = o + (long long)row * ncols;
    __shared__ float red[256];
    float s = 0.f;
    for (int c = threadIdx.x; c < ncols; c += 256) { float t = xr[c]; s += t * t; }
    red[threadIdx.x] = s; __syncthreads();
    for (int st = 128; st > 0; st >>= 1) {
        if (threadIdx.x < st) red[threadIdx.x] += red[threadIdx.x + st];
        __syncthreads();
    }
    float rms = rsqrtf(red[0] / (float)ncols + 1e-6f);
    for (int c = threadIdx.x; c < ncols; c += 256) orow[c] = xr[c] * rms * w[c];
}

__global__ void qknorm_rope_kernel(float* __restrict__ q, float* __restrict__ k,
                                   const float* __restrict__ qw, const float* __restrict__ kw,
                                   const float* __restrict__ ropec,
                                   const float* __restrict__ ropes) {
    int slot = blockIdx.x;
    int t    = blockIdx.y;
    float* vec; const float* w;
    if (slot < NHQ) { vec = q + (long long)t * (NHQ*HDHD) + slot * HDHD; w = qw; }
    else            { vec = k + (long long)t * (NKVH*HDHD) + (slot - NHQ) * HDHD; w = kw; }
    int d = threadIdx.x;
    float v = vec[d];
    float s = v * v;
    #pragma unroll
    for (int o = 16; o > 0; o >>= 1) s += __shfl_xor_sync(0xffffffffu, s, o);
    __shared__ float red[4];
    if ((d & 31) == 0) red[d >> 5] = s;
    __syncthreads();
    float tot = red[0] + red[1] + red[2] + red[3];
    float rms = rsqrtf(tot / 128.f + 1e-6f);
    float nv = v * rms * w[d];
    __shared__ float sv[128];
    sv[d] = nv;
    __syncthreads();
    int d2 = d & 63;
    float c  = ropec[t * 64 + d2];
    float sn = ropes[t * 64 + d2];
    float other = (d < 64) ? -sv[d + 64] : sv[d - 64];
    vec[d] = nv * c + other * sn;
}

// ---------------- flash attention: scores+softmax+AV fused ----------------
#define FBR 128
#define FBC 64
#define QSTR 164
#define KSTR 164
#define VSTR 136
#define PSTR 68
__global__ void __launch_bounds__(256, 1)
flash_kernel(const float* __restrict__ q, const float* __restrict__ k,
             const float* __restrict__ v, float* __restrict__ attn, float scale) {
    int rb = blockIdx.x;
    int h  = blockIdx.y;
    int kv = h >> 3;
    int tid = threadIdx.x;
    int warp = tid >> 5, lane = tid & 31;
    int g = lane >> 2, t = lane & 3;
    int wr  = (warp >> 2) * 64;
    int wcS = (warp & 3) * 16;
    int wcO = (warp & 3) * 32;
    int wq  = warp & 3;

    extern __shared__ float sm[];
    float* Qs   = sm;
    float* Ks   = Qs + FBR*QSTR;
    float* Vs   = Ks + FBC*KSTR;
    float* Ps   = Vs + FBC*VSTR;
    float* redm = Ps + FBR*PSTR;
    float* redl = redm + 4*FBR;
    float* m_s  = redl + 4*FBR;
    float* l_s  = m_s + FBR;

    int row0 = rb * FBR;

    for (int i = tid; i < FBR; i += 256) { m_s[i] = -1e30f; l_s[i] = 0.f; }

    for (int i = tid; i < FBR * 32; i += 256) {
        int r = i >> 5, cq = i & 31;
        cpasync16(Qs + r*QSTR + cq*4,
                  q + (long long)(row0 + r)*(NHQ*HDHD) + h*HDHD + cq*4, 16);
    }
    for (int i = tid; i < FBC * 32; i += 256) {
        int n = i >> 5, cq = i & 31;
        cpasync16(Ks + n*KSTR + cq*4,
                  k + (long long)n*(NKVH*HDHD) + kv*HDHD + cq*4, 16);
        cpasync16(Vs + n*VSTR + cq*4,
                  v + (long long)n*(NKVH*HDHD) + kv*HDHD + cq*4, 16);
    }
    cpasync_commit();

    float accO[4][4][4];
    #pragma unroll
    for (int i1 = 0; i1 < 4; i1++)
        #pragma unroll
        for (int i2 = 0; i2 < 4; i2++)
            #pragma unroll
            for (int i3 = 0; i3 < 4; i3++) accO[i1][i2][i3] = 0.f;

    int jmax = 2*rb + 1;

    for (int j = 0; j <= jmax; j++) {
        asm volatile("cp.async.wait_group 0;" ::: "memory");
        __syncthreads();

        // ---- S = Q @ K_j^T ----
        float accS[4][2][4];
        #pragma unroll
        for (int i1 = 0; i1 < 4; i1++)
            #pragma unroll
            for (int i2 = 0; i2 < 2; i2++)
                #pragma unroll
                for (int i3 = 0; i3 < 4; i3++) accS[i1][i2][i3] = 0.f;
        #pragma unroll
        for (int ks = 0; ks < 16; ks++) {
            int kb = ks * 8;
            uint32_t a[4][4], b[2][2];
            #pragma unroll
            for (int fm = 0; fm < 4; fm++) {
                int m0 = wr + fm * 16;
                a[fm][0] = rnd(Qs[(m0 + g    ) * QSTR + kb + t    ]);
                a[fm][1] = rnd(Qs[(m0 + g + 8) * QSTR + kb + t    ]);
                a[fm][2] = rnd(Qs[(m0 + g    ) * QSTR + kb + t + 4]);
                a[fm][3] = rnd(Qs[(m0 + g + 8) * QSTR + kb + t + 4]);
            }
            #pragma unroll
            for (int fn = 0; fn < 2; fn++) {
                int n0 = wcS + fn * 8 + g;
                b[fn][0] = rnd(Ks[n0 * KSTR + kb + t    ]);
                b[fn][1] = rnd(Ks[n0 * KSTR + kb + t + 4]);
            }
            #pragma unroll
            for (int fm = 0; fm < 4; fm++)
                #pragma unroll
                for (int fn = 0; fn < 2; fn++)
                    MMA_TF32(accS[fm][fn], a[fm], b[fn]);
        }

        // scale + causal mask + per-row max
        int colbase = j * FBC + wcS;
        #pragma unroll
        for (int fm = 0; fm < 4; fm++)
            #pragma unroll
            for (int rr = 0; rr < 2; rr++) {
                int row = row0 + wr + fm*16 + g + rr*8;
                float mx = -1e30f;
                #pragma unroll
                for (int fn = 0; fn < 2; fn++)
                    #pragma unroll
                    for (int cc = 0; cc < 2; cc++) {
                        float sv = accS[fm][fn][rr*2 + cc] * scale;
                        int col = colbase + fn*8 + t*2 + cc;
                        if (col > row) sv = -1e30f;
                        accS[fm][fn][rr*2 + cc] = sv;
                        mx = fmaxf(mx, sv);
                    }
                mx = fmaxf(mx, __shfl_xor_sync(0xffffffffu, mx, 1));
                mx = fmaxf(mx, __shfl_xor_sync(0xffffffffu, mx, 2));
                if (t == 0) redm[wq*FBR + wr + fm*16 + g + rr*8] = mx;
            }
        __syncthreads();

        if (j < jmax) {
            for (int i = tid; i < FBC * 32; i += 256) {
                int n = i >> 5, cq = i & 31;
                cpasync16(Ks + n*KSTR + cq*4,
                          k + (long long)((j+1)*FBC + n)*(NKVH*HDHD) + kv*HDHD + cq*4, 16);
            }
        }
        cpasync_commit();

        float mnew[4][2], esr[4][2];
        #pragma unroll
        for (int fm = 0; fm < 4; fm++)
            #pragma unroll
            for (int rr = 0; rr < 2; rr++) {
                int row = wr + fm*16 + g + rr*8;
                float mo = m_s[row];
                float mn = fmaxf(fmaxf(redm[row], redm[FBR + row]),
                                 fmaxf(redm[2*FBR + row], redm[3*FBR + row]));
                mn = fmaxf(mn, mo);
                mnew[fm][rr] = mn;
                esr[fm][rr] = __expf(mo - mn);
            }
        #pragma unroll
        for (int fm = 0; fm < 4; fm++)
            #pragma unroll
            for (int rr = 0; rr < 2; rr++) {
                int row = wr + fm*16 + g + rr*8;
                float lsum = 0.f;
                #pragma unroll
                for (int fn = 0; fn < 2; fn++)
                    #pragma unroll
                    for (int cc = 0; cc < 2; cc++) {
                        float p = __expf(accS[fm][fn][rr*2 + cc] - mnew[fm][rr]);
                        lsum += p;
                        Ps[row * PSTR + wcS + fn*8 + t*2 + cc] = p;
                    }
                lsum += __shfl_xor_sync(0xffffffffu, lsum, 1);
                lsum += __shfl_xor_sync(0xffffffffu, lsum, 2);
                if (t == 0) redl[wq*FBR + row] = lsum;
            }
        #pragma unroll
        for (int fm = 0; fm < 4; fm++)
            #pragma unroll
            for (int fn = 0; fn < 4; fn++)
                #pragma unroll
                for (int r = 0; r < 4; r++)
                    accO[fm][fn][r] *= esr[fm][r >> 1];
        __syncthreads();

        if (wq == 0 && t == 0) {
            #pragma unroll
            for (int fm = 0; fm < 4; fm++)
                #pragma unroll
                for (int rr = 0; rr < 2; rr++) {
                    int row = wr + fm*16 + g + rr*8;
                    l_s[row] = l_s[row] * esr[fm][rr]
                             + redl[row] + redl[FBR + row]
                             + redl[2*FBR + row] + redl[3*FBR + row];
                    m_s[row] = mnew[fm][rr];
                }
        }

        // ---- O += P @ V ----
        #pragma unroll
        for (int ks = 0; ks < 8; ks++) {
            int kb = ks * 8;
            uint32_t a[4][4], b[4][2];
            #pragma unroll
            for (int fm = 0; fm < 4; fm++) {
                int m0 = wr + fm * 16;
                a[fm][0] = rnd(Ps[(m0 + g    ) * PSTR + kb + t    ]);
                a[fm][1] = rnd(Ps[(m0 + g + 8) * PSTR + kb + t    ]);
                a[fm][2] = rnd(Ps[(m0 + g    ) * PSTR + kb + t + 4]);
                a[fm][3] = rnd(Ps[(m0 + g + 8) * PSTR + kb + t + 4]);
            }
            #pragma unroll
            for (int fn = 0; fn < 4; fn++) {
                int n0 = wcO + fn * 8 + g;
                b[fn][0] = rnd(Vs[(kb + t    ) * VSTR + n0]);
                b[fn][1] = rnd(Vs[(kb + t + 4) * VSTR + n0]);
            }
            #pragma unroll
            for (int fm = 0; fm < 4; fm++)
                #pragma unroll
                for (int fn = 0; fn < 4; fn++)
                    MMA_TF32(accO[fm][fn], a[fm], b[fn]);
        }
        __syncthreads();

        if (j < jmax) {
            for (int i = tid; i < FBC * 32; i += 256) {
                int n = i >> 5, cq = i & 31;
                cpasync16(Vs + n*VSTR + cq*4,
                          v + (long long)((j+1)*FBC + n)*(NKVH*HDHD) + kv*HDHD + cq*4, 16);
            }
        }
        cpasync_commit();
    }

    __syncthreads();
    #pragma unroll
    for (int fm = 0; fm < 4; fm++)
        #pragma unroll
        for (int rr = 0; rr < 2; rr++) {
            int row = wr + fm*16 + g + rr*8;
            float inv = 1.f / l_s[row];
            float* op = attn + (long long)(row0 + row)*(NHQ*HDHD) + h*HDHD;
            #pragma unroll
            for (int fn = 0; fn < 4; fn++) {
                int c = wcO + fn*8 + t*2;
                op[c]     = accO[fm][fn][rr*2    ] * inv;
                op[c + 1] = accO[fm][fn][rr*2 + 1] * inv;
            }
        }
}

// ---------------- fused gate logits + softmax + top-8 (warp per token) ----------------
__global__ void gate_topk_kernel(const float* __restrict__ h2, const float* __restrict__ Wg,
                                 float* __restrict__ tw, int* __restrict__ te) {
    int w = threadIdx.x >> 5, lane = threadIdx.x & 31;
    int t = blockIdx.x * 8 + w;
    const float* xr = h2 + (long long)t * HDM;
    float acc = 0.f;
    for (int k0 = 0; k0 < HDM; k0 += 32) {
        float tk = xr[k0 + lane];
        #pragma unroll
        for (int j = 0; j < 32; j++) {
            float tv = __shfl_sync(0xffffffffu, tk, j);
            acc += tv * Wg[(k0 + j) * NE + lane];
        }
    }
    // softmax over 32 lanes (lane == expert)
    float m = acc;
    #pragma unroll
    for (int o = 16; o > 0; o >>= 1) m = fmaxf(m, __shfl_xor_sync(0xffffffffu, m, o));
    float p = expf(acc - m);
    float s = p;
    #pragma unroll
    for (int o = 16; o > 0; o >>= 1) s += __shfl_xor_sync(0xffffffffu, s, o);
    float inv = 1.f / s;
    // top-8 with lowest-index tie-break
    float pc = p;
    #pragma unroll
    for (int kk = 0; kk < TOPK; kk++) {
        float bp = pc; int bl = lane;
        #pragma unroll
        for (int o = 16; o > 0; o >>= 1) {
            float op = __shfl_xor_sync(0xffffffffu, bp, o);
            int   ol = __shfl_xor_sync(0xffffffffu, bl, o);
            if (op > bp || (op == bp && ol < bl)) { bp = op; bl = ol; }
        }
        if (lane == 0) { te[t * TOPK + kk] = bl; tw[t * TOPK + kk] = bp * inv; }
        if (lane == bl) pc = -1e30f;
    }
}

__global__ void count_kernel(const int* __restrict__ te, int* __restrict__ counts) {
    int p = blockIdx.x * 256 + threadIdx.x;
    if (p < NPAIR) atomicAdd(&counts[te[p]], 1);
}

__global__ void scan_kernel(const int* __restrict__ counts, int* __restrict__ offsets) {
    if (threadIdx.x == 0) {
        int s = 0;
        for (int e = 0; e < NE; e++) { offsets[e] = s; s += counts[e]; }
    }
}

__global__ void assign_kernel(const int* __restrict__ te, const int* __restrict__ offsets,
                              int* __restrict__ cursor, int* __restrict__ btok,
                              int* __restrict__ ppos) {
    int p = blockIdx.x * 256 + threadIdx.x;
    if (p >= NPAIR) return;
    int e = te[p];
    int pos = offsets[e] + atomicAdd(&cursor[e], 1);
    btok[pos] = p >> 3;
    ppos[p] = pos;
}

__global__ void combine_kernel(const float* __restrict__ h, const float* __restrict__ ybuf,
                               const int* __restrict__ ppos, const float* __restrict__ tw,
                               float* __restrict__ out) {
    int t = blockIdx.x;
    __shared__ int   pos[TOPK];
    __shared__ float ww[TOPK];
    if (threadIdx.x < TOPK) {
        pos[threadIdx.x] = ppos[t * TOPK + threadIdx.x];
        ww[threadIdx.x]  = tw[t * TOPK + threadIdx.x];
    }
    __syncthreads();
    const float4* h4 = (const float4*)(h + (long long)t * HDM);
    float4* o4 = (float4*)(out + (long long)t * HDM);
    for (int c = threadIdx.x; c < HDM / 4; c += 256) {
        float4 a = h4[c];
        #pragma unroll
        for (int kk = 0; kk < TOPK; kk++) {
            float4 b = ((const float4*)(ybuf + (long long)pos[kk] * HDM))[c];
            float wv = ww[kk];
            a.x += wv * b.x; a.y += wv * b.y; a.z += wv * b.z; a.w += wv * b.w;
        }
        o4[c] = a;
    }
}

// ---------------- tf32 tensor-core GEMM, BK=64, 2-stage, one sync per chunk ----------------
// modes: 0 = plain (Wo, with optional residual); 2 = contiguous expert rows (MoE down);
//        3 = fused QKV
#define BKK 64
#define ASTR 68
template<int BN>
__global__ void __launch_bounds__(256, 1)
gemm_tc(const float* __restrict__ A, const float* __restrict__ B, float* __restrict__ C,
        const float* __restrict__ resid,
        int M, int K, int lda, int ldb, int ldc,
        long long sB, int mode,
        const int* __restrict__ counts, const int* __restrict__ offsets,
        const float* __restrict__ B2, float* __restrict__ C2,
        const float* __restrict__ B3, float* __restrict__ C3) {
    constexpr int BM = 128;
    constexpr int WN = BN / 4;
    constexpr int FM = 4, FN = WN / 8;
    constexpr int ASZ = BM * ASTR;
    constexpr int BSZ = BKK * (BN + 8);

    extern __shared__ float smem[];
    float* sA_ = smem;
    float* sB_ = smem + 2 * ASZ;

    int z = blockIdx.z;
    int tid = threadIdx.x;
    int row0 = blockIdx.y * BM;
    int col0 = blockIdx.x * BN;

    const float* Az = A;
    const float* Bz;
    float* Cz;
    if (mode == 3) {
        if (z < 16)      { Bz = B;  Cz = C;  ldb = ldc = NHQ*HDHD;  col0 = z * BN; }
        else if (z < 18) { Bz = B2; Cz = C2; ldb = ldc = NKVH*HDHD; col0 = (z - 16) * BN; }
        else             { Bz = B3; Cz = C3; ldb = ldc = NKVH*HDHD; col0 = (z - 18) * BN; }
    } else if (mode == 2) {
        Bz = B + (long long)z * sB;
        Cz = C;
    } else {
        Bz = B;
        Cz = C;
    }

    int cnt = M, start = 0;
    if (mode == 2) { cnt = counts[z]; start = offsets[z]; }
    if (mode == 2 && row0 >= cnt) return;

    int warp = tid >> 5, lane = tid & 31;
    int wr = (warp >> 2) * 64, wc = (warp & 3) * WN;
    int g = lane >> 2, t = lane & 3;

    float acc[FM][FN][4];
    #pragma unroll
    for (int i = 0; i < FM; i++)
        #pragma unroll
        for (int j = 0; j < FN; j++)
            #pragma unroll
            for (int r = 0; r < 4; r++) acc[i][j][r] = 0.f;

    auto loadTiles = [&](int st, int k0) {
        float* a = sA_ + st * ASZ;
        float* b = sB_ + st * BSZ;
        #pragma unroll
        for (int i = tid; i < BM * 16; i += 256) {
            int r = i >> 4, kq = i & 15;
            bool val = (row0 + r < cnt);
            long long ar = 0;
            if (val) ar = (mode == 2) ? (start + row0 + r) : (row0 + r);
            cpasync16(a + r * ASTR + kq * 4, Az + ar * lda + k0 + kq * 4, val ? 16 : 0);
        }
        #pragma unroll
        for (int i = tid; i < BKK * (BN / 4); i += 256) {
            int kk = i / (BN / 4), nq = i % (BN / 4);
            cpasync16(b + kk * (BN + 8) + nq * 4,
                      Bz + (long long)(k0 + kk) * ldb + col0 + nq * 4, 16);
        }
    };

    auto compute = [&](int st) {
        const float* a_ = sA_ + st * ASZ;
        const float* b_ = sB_ + st * BSZ;
        #pragma unroll
        for (int ks = 0; ks < 8; ks++) {
            int kb = ks * 8;
            uint32_t a[FM][4], b[FN][2];
            #pragma unroll
            for (int fm = 0; fm < FM; fm++) {
                int m0 = wr + fm * 16;
                a[fm][0] = rnd(a_[(m0 + g) * ASTR + kb + t]);
                a[fm][1] = rnd(a_[(m0 + g + 8) * ASTR + kb + t]);
                a[fm][2] = rnd(a_[(m0 + g) * ASTR + kb + t + 4]);
                a[fm][3] = rnd(a_[(m0 + g + 8) * ASTR + kb + t + 4]);
            }
            #pragma unroll
            for (int fn = 0; fn < FN; fn++) {
                int n0 = wc + fn * 8 + g;
                b[fn][0] = rnd(b_[(kb + t) * (BN + 8) + n0]);
                b[fn][1] = rnd(b_[(kb + t + 4) * (BN + 8) + n0]);
            }
            #pragma unroll
            for (int fm = 0; fm < FM; fm++)
                #pragma unroll
                for (int fn = 0; fn < FN; fn++)
                    MMA_TF32(acc[fm][fn], a[fm], b[fn]);
        }
    };

    int nk = K / BKK;
    loadTiles(0, 0);
    cpasync_commit();
    for (int ks = 0; ks < nk; ks++) {
        asm volatile("cp.async.wait_group 0;" ::: "memory");
        __syncthreads();
        if (ks + 1 < nk) {
            loadTiles((ks + 1) & 1, (ks + 1) * BKK);
            cpasync_commit();
        }
        compute(ks & 1);
    }

    // ---- epilogue ----
    #pragma unroll
    for (int fm = 0; fm < FM; fm++) {
        #pragma unroll
        for (int rr = 0; rr < 2; rr++) {
            int lr = wr + fm * 16 + g + rr * 8;
            if (row0 + lr >= cnt) continue;
            long long crow = (mode == 2) ? (long long)(start + row0 + lr)
                                         : (long long)(row0 + lr);
            float* cp = Cz + crow * ldc;
            const float* rp = resid ? (resid + (long long)(row0 + lr) * ldc) : nullptr;
            #pragma unroll
            for (int fn = 0; fn < FN; fn++) {
                int c = col0 + wc + fn * 8 + t * 2;
                float v0 = acc[fm][fn][rr * 2 + 0];
                float v1 = acc[fm][fn][rr * 2 + 1];
                if (rp) { v0 += rp[c]; v1 += rp[c + 1]; }
                cp[c] = v0;
                cp[c + 1] = v1;
            }
        }
    }
}

// ---------------- MoE up GEMM with fused SiLU (BK=64, 2-stage) ----------------
__global__ void __launch_bounds__(256, 1)
moe_up_fused(const float* __restrict__ h2, const float* __restrict__ Wgu,
             float* __restrict__ act,
             const int* __restrict__ counts, const int* __restrict__ offsets,
             const int* __restrict__ btok) {
    constexpr int BM = 128;
    constexpr int ASZ = BM * ASTR;
    constexpr int BSZ = BKK * (256 + 8);

    extern __shared__ float smem[];
    float* sA_ = smem;
    float* sB_ = smem + 2 * ASZ;
    __shared__ int stok[BM];

    int e = blockIdx.z;
    int tid = threadIdx.x;
    int row0 = blockIdx.y * BM;
    int col0 = blockIdx.x * 128;

    int cnt = counts[e], start = offsets[e];
    if (row0 >= cnt) return;

    const float* Bz = Wgu + (long long)e * (HDM * 2 * IDIM);

    for (int i = tid; i < BM; i += 256)
        stok[i] = (row0 + i < cnt) ? btok[start + row0 + i] : 0;
    __syncthreads();

    int warp = tid >> 5, lane = tid & 31;
    int wr = (warp >> 2) * 64, wcg = (warp & 3) * 32;
    int g = lane >> 2, t = lane & 3;

    float acc[4][8][4];
    #pragma unroll
    for (int i = 0; i < 4; i++)
        #pragma unroll
        for (int j = 0; j < 8; j++)
            #pragma unroll
            for (int r = 0; r < 4; r++) acc[i][j][r] = 0.f;

    auto loadTiles = [&](int st, int k0) {
        float* a = sA_ + st * ASZ;
        float* b = sB_ + st * BSZ;
        #pragma unroll
        for (int i = tid; i < BM * 16; i += 256) {
            int r = i >> 4, kq = i & 15;
            bool val = (row0 + r < cnt);
            long long ar = val ? stok[r] : 0;
            cpasync16(a + r * ASTR + kq * 4, h2 + ar * HDM + k0 + kq * 4, val ? 16 : 0);
        }
        #pragma unroll
        for (int i = tid; i < BKK * 64; i += 256) {
            int kk = i >> 6, nq = i & 63;
            int gc = (nq < 32) ? (col0 + nq * 4) : (IDIM + col0 + (nq - 32) * 4);
            cpasync16(b + kk * 264 + nq * 4,
                      Bz + (long long)(k0 + kk) * (2 * IDIM) + gc, 16);
        }
    };

    auto compute = [&](int st) {
        const float* a_ = sA_ + st * ASZ;
        const float* b_ = sB_ + st * BSZ;
        #pragma unroll
        for (int ks = 0; ks < 8; ks++) {
            int kb = ks * 8;
            uint32_t a[4][4], b[8][2];
            #pragma unroll
            for (int fm = 0; fm < 4; fm++) {
                int m0 = wr + fm * 16;
                a[fm][0] = rnd(a_[(m0 + g) * ASTR + kb + t]);
                a[fm][1] = rnd(a_[(m0 + g + 8) * ASTR + kb + t]);
                a[fm][2] = rnd(a_[(m0 + g) * ASTR + kb + t + 4]);
                a[fm][3] = rnd(a_[(m0 + g + 8) * ASTR + kb + t + 4]);
            }
            #pragma unroll
            for (int fn = 0; fn < 8; fn++) {
                int n0 = (fn < 4) ? (wcg + fn * 8 + g)
                                  : (128 + wcg + (fn - 4) * 8 + g);
                b[fn][0] = rnd(b_[(kb + t) * 264 + n0]);
                b[fn][1] = rnd(b_[(kb + t + 4) * 264 + n0]);
            }
            #pragma unroll
            for (int fm = 0; fm < 4; fm++)
                #pragma unroll
                for (int fn = 0; fn < 8; fn++)
                    MMA_TF32(acc[fm][fn], a[fm], b[fn]);
        }
    };

    int nk = HDM / BKK;
    loadTiles(0, 0);
    cpasync_commit();
    for (int ks = 0; ks < nk; ks++) {
        asm volatile("cp.async.wait_group 0;" ::: "memory");
        __syncthreads();
        if (ks + 1 < nk) {
            loadTiles((ks + 1) & 1, (ks + 1) * BKK);
            cpasync_commit();
        }
        compute(ks & 1);
    }

    // ---- epilogue: act = silu(gate) * up ----
    #pragma unroll
    for (int fm = 0; fm < 4; fm++) {
        #pragma unroll
        for (int rr = 0; rr < 2; rr++) {
            int lr = wr + fm * 16 + g + rr * 8;
            if (row0 + lr >= cnt) continue;
            float* ap = act + (long long)(start + row0 + lr) * IDIM;
            #pragma unroll
            for (int fn = 0; fn < 4; fn++) {
                int c = col0 + wcg + fn * 8 + t * 2;
                #pragma unroll
                for (int cc = 0; cc < 2; cc++) {
                    float gv = acc[fm][fn][rr * 2 + cc];
                    float uv = acc[fm][fn + 4][rr * 2 + cc];
                    ap[c + cc] = (gv / (1.f + __expf(-gv))) * uv;
                }
            }
        }
    }
}

// ---------------- host launcher ----------------
static void* symaddr(const void* s) { void* p = nullptr; cudaGetSymbolAddress(&p, s); return p; }

extern "C" void kernel_launch(void* const* d_in, const int* in_sizes, int n_in,
                              void* d_out, int out_size) {
    const float* x   = (const float*)d_in[0];
    const float* ln1 = (const float*)d_in[1];
    const float* ln2 = (const float*)d_in[2];
    const float* qnw = (const float*)d_in[3];
    const float* knw = (const float*)d_in[4];
    const float* Wq  = (const float*)d_in[5];
    const float* Wk  = (const float*)d_in[6];
    const float* Wv  = (const float*)d_in[7];
    const float* Wo  = (const float*)d_in[8];
    const float* Wg  = (const float*)d_in[9];
    const float* Wgu = (const float*)d_in[10];
    const float* Wd  = (const float*)d_in[11];
    float* out = (float*)d_out;

    float* h1   = (float*)symaddr(g_h1);
    float* q    = (float*)symaddr(g_q);
    float* k    = (float*)symaddr(g_k);
    float* v    = (float*)symaddr(g_v);
    float* attn = (float*)symaddr(g_attn);
    float* h    = (float*)symaddr(g_h);
    float* h2   = (float*)symaddr(g_h2);
    float* tw   = (float*)symaddr(g_tw);
    int*   te   = (int*)symaddr(g_te);
    int*   cnts = (int*)symaddr(g_counts);
    int*   offs = (int*)symaddr(g_offsets);
    int*   cur  = (int*)symaddr(g_cursor);
    int*   btok = (int*)symaddr(g_btok);
    int*   ppos = (int*)symaddr(g_ppos);
    float* act  = (float*)symaddr(g_act);
    float* ybuf = (float*)symaddr(g_ybuf);
    float* rc   = (float*)symaddr(g_ropec);
    float* rs   = (float*)symaddr(g_ropes);

    const float scale = 0.08838834764831843f;   // 1/sqrt(128)

    const size_t smem128 = (size_t)(2 * 128 * ASTR + 2 * (BKK * (128 + 8))) * 4;  // 139264
    const size_t smem256 = (size_t)(2 * 128 * ASTR + 2 * (BKK * (256 + 8))) * 4;  // 204800
    const size_t smemFA  = (size_t)(FBR*QSTR + FBC*KSTR + FBC*VSTR + FBR*PSTR
                                    + 8*FBR + 2*FBR) * 4;                          // 200704
    static int attrDone = 0;
    if (!attrDone) {
        cudaFuncSetAttribute((const void*)gemm_tc<128>,
                             cudaFuncAttributeMaxDynamicSharedMemorySize, 144 * 1024);
        cudaFuncSetAttribute((const void*)gemm_tc<256>,
                             cudaFuncAttributeMaxDynamicSharedMemorySize, 205 * 1024);
        cudaFuncSetAttribute((const void*)moe_up_fused,
                             cudaFuncAttributeMaxDynamicSharedMemorySize, 205 * 1024);
        cudaFuncSetAttribute((const void*)flash_kernel,
                             cudaFuncAttributeMaxDynamicSharedMemorySize, 205 * 1024);
        attrDone = 1;
    }

    zero32_kernel<<<1, 32>>>(cnts, cur);
    rope_table_kernel<<<(SQ*64 + 255)/256, 256>>>(rc, rs);

    // ---- attention ----
    rmsnorm_kernel<<<SQ, 256>>>(x, ln1, h1, HDM);

    // fused QKV projection: BN=256, grid (1,8,20)
    gemm_tc<256><<<dim3(1, 8, 20), 256, smem256>>>(h1, Wq, q, nullptr,
        SQ, HDM, HDM, 0, 0, 0, 3, nullptr, nullptr, Wk, k, Wv, v);

    qknorm_rope_kernel<<<dim3(NHQ + NKVH, SQ), 128>>>(q, k, qnw, knw, rc, rs);

    // flash attention (scores + softmax + AV fused)
    flash_kernel<<<dim3(SQ/FBR, NHQ), 256, smemFA>>>(q, k, v, attn, scale);

    // h = x + attn @ Wo   (residual fused)
    gemm_tc<128><<<dim3(16, 8, 1), 256, smem128>>>(attn, Wo, h, x,
        SQ, NHQ*HDHD, NHQ*HDHD, HDM, HDM, 0, 0,
        nullptr, nullptr, nullptr, nullptr, nullptr, nullptr);

    // ---- MoE ----
    rmsnorm_kernel<<<SQ, 256>>>(h, ln2, h2, HDM);

    gate_topk_kernel<<<SQ/8, 256>>>(h2, Wg, tw, te);
    count_kernel<<<(NPAIR + 255) / 256, 256>>>(te, cnts);
    scan_kernel<<<1, 32>>>(cnts, offs);
    assign_kernel<<<(NPAIR + 255) / 256, 256>>>(te, offs, cur, btok, ppos);

    // MoE up/gate + SiLU fused: grid (6, 8, 32)
    moe_up_fused<<<dim3(IDIM/128, 8, NE), 256, smem256>>>(h2, Wgu, act, cnts, offs, btok);

    // MoE down: grid (8, 8, 32)
    gemm_tc<256><<<dim3(HDM/256, 8, NE), 256, smem256>>>(act, Wd, ybuf, nullptr,
        SQ, IDIM, IDIM, HDM, HDM, (long long)IDIM*HDM, 2,
        cnts, offs, nullptr, nullptr, nullptr, nullptr);

    combine_kernel<<<SQ, 256>>>(h, ybuf, ppos, tw, out);
}